// round 6
// baseline (speedup 1.0000x reference)
#include <cuda_runtime.h>
#include <stdint.h>

// Problem constants
#define Bb    32768
#define Ll    7
#define Tt    6
#define Hh    256
#define TS    5                 // only edges t=0..4 are live
#define MROWS (Bb * TS)         // 163840
#define MCTX  (Bb * Ll)         // 229376
#define HALF_N 114688u          // (Bb*Ll)/2 for original threefry split

// PRNG stream variant:
//  1: partitionable, bits = o0 ^ o1   (modern JAX default, 32-bit fold)
//  2: partitionable, bits = o1        (low word of 64-bit block)
//  0: original concat-split scheme
#define PRNG_MODE 1

// ---------------- device scratch (static, allocation-free) ----------------
__device__ float g_G   [(size_t)MROWS * 512];   // gathered [enc_h | enc_v], partitioned
__device__ float g_Edge[(size_t)MROWS * Hh];    // edge_t rows indexed by bt = b*5+t
__device__ float g_S   [(size_t)MROWS * Hh];    // edge @ W_edge^T
__device__ float g_qt  [Bb * Hh];
__device__ float g_inp [Bb * Hh];
__device__ float g_att2[MCTX];
__device__ float g_colmax[Ll];
__device__ float g_colsum[Ll];
__device__ float g_logZ[Ll];
__device__ int   g_rmap[MROWS];   // G row -> bt
__device__ int   g_hv  [MROWS];   // packed h | v<<8
__device__ int   g_cntA;          // rows with cond (t==0)
__device__ int   g_cntB;
__device__ int   g_is64;          // xes dtype flag

// ---------------- small helpers ----------------
__device__ __forceinline__ unsigned long long pack2(float x, float y) {
    unsigned long long r;
    asm("mov.b64 %0, {%1, %2};" : "=l"(r) : "r"(__float_as_uint(x)), "r"(__float_as_uint(y)));
    return r;
}
__device__ __forceinline__ float2 unpack2(unsigned long long v) {
    unsigned int lo, hi;
    asm("mov.b64 {%0, %1}, %2;" : "=r"(lo), "=r"(hi) : "l"(v));
    float2 f; f.x = __uint_as_float(lo); f.y = __uint_as_float(hi); return f;
}
#define FMA2(acc, a, b) asm("fma.rn.f32x2 %0, %1, %2, %0;" : "+l"(acc) : "l"(a), "l"(b))

__device__ __forceinline__ uint32_t rotl32(uint32_t v, int r) { return (v << r) | (v >> (32 - r)); }

// JAX Threefry-2x32-20, key = (0, 42)  [jax.random.key(42)]
__device__ __forceinline__ void tf2x32(uint32_t x0, uint32_t x1, uint32_t& o0, uint32_t& o1) {
    const uint32_t k0 = 0u, k1 = 42u, k2 = 0u ^ 42u ^ 0x1BD11BDAu;
    x0 += k0; x1 += k1;
#define TFR(r) { x0 += x1; x1 = rotl32(x1, (r)); x1 ^= x0; }
    TFR(13) TFR(15) TFR(26) TFR(6)   x0 += k1; x1 += k2 + 1u;
    TFR(17) TFR(29) TFR(16) TFR(24)  x0 += k2; x1 += k0 + 2u;
    TFR(13) TFR(15) TFR(26) TFR(6)   x0 += k0; x1 += k1 + 3u;
    TFR(17) TFR(29) TFR(16) TFR(24)  x0 += k1; x1 += k2 + 4u;
    TFR(13) TFR(15) TFR(26) TFR(6)   x0 += k2; x1 += k0 + 5u;
#undef TFR
    o0 = x0; o1 = x1;
}

// 32 random bits for flat element n, per JAX's threefry_random_bits
__device__ __forceinline__ uint32_t jax_bits(uint32_t n) {
#if PRNG_MODE == 1
    uint32_t o0, o1; tf2x32(0u, n, o0, o1); return o0 ^ o1;
#elif PRNG_MODE == 2
    uint32_t o0, o1; tf2x32(0u, n, o0, o1); return o1;
#else
    uint32_t o0, o1;
    if (n < HALF_N) { tf2x32(n, HALF_N + n, o0, o1); return o0; }
    else            { tf2x32(n - HALF_N, n, o0, o1); return o1; }
#endif
}

// ---------------- kernels ----------------
__global__ void k_init() { g_cntA = 0; g_cntB = 0; }

// Detect whether xes is int64 (odd int32 words all zero) or int32.
__global__ void k_detect(const int* __restrict__ xes) {
    __shared__ int any;
    if (threadIdx.x == 0) any = 0;
    __syncthreads();
    if (xes[2 * threadIdx.x + 1] != 0) any = 1;   // 128 threads -> words 1,3,...,255
    __syncthreads();
    if (threadIdx.x == 0) g_is64 = !any;
}

// partition (b,t) rows by cond = (xes[b,t,2] == 0); cond rows from front, else from back
__global__ void k_map(const int* __restrict__ xes) {
    int bt = blockIdx.x * blockDim.x + threadIdx.x;
    if (bt >= MROWS) return;
    int b = bt / TS, t = bt - b * TS;
    int base = (b * Tt + t) * 3;
    int s = g_is64 ? 2 : 1;
    int h  = xes[(base + 0) * s];
    int v  = xes[(base + 1) * s];
    int tt = xes[(base + 2) * s];
    int g;
    if (tt == 0) g = atomicAdd(&g_cntA, 1);
    else         g = MROWS - 1 - atomicAdd(&g_cntB, 1);
    g_rmap[g] = bt;
    g_hv[g]   = h | (v << 8);
}

// materialize G[g, 0:256] = enc[b, h, :], G[g, 256:512] = enc[b, v, :]
__global__ void k_gather(const float* __restrict__ enc) {
    int i = blockIdx.x * blockDim.x + threadIdx.x;   // MROWS*128 float4 slots
    int g  = i >> 7;
    int c  = (i & 127) << 2;
    int hv = g_hv[g];
    int bt = g_rmap[g];
    int b  = bt / TS;
    int row = (c < 256) ? (hv & 0xff) : (hv >> 8);
    int cc  = c & 255;
    float4 val = *(const float4*)(enc + (size_t)(b * Ll + row) * 256 + cc);
    *(float4*)(g_G + (size_t)g * 512 + c) = val;
}

// Generic 128x128x16 fp32 SGEMM with f32x2 FMAs.
// MODE 0: edges, cond partition (A=g_G, K=512, W=[W0|W1], rows r< cntA, scatter by rmap)
// MODE 1: edges, else partition (rows r >= cntA)
// MODE 2: S = Edge @ W_edge^T
// MODE 3: inp = qt @ W_in^T + b_in
template <int MODE>
__global__ void __launch_bounds__(256) sgemm128(const float* __restrict__ W0,
                                                const float* __restrict__ W1,
                                                const float* __restrict__ bias) {
    const int row0 = blockIdx.x * 128;
    const int col0 = blockIdx.y * 128;
    int bound = 0;
    if (MODE <= 1) {
        bound = g_cntA;
        if (MODE == 0 && row0 >= bound) return;
        if (MODE == 1 && row0 + 128 <= bound) return;
    }
    const int K   = (MODE <= 1) ? 512 : 256;
    const int lda = (MODE <= 1) ? 512 : 256;
    const float* A = (MODE <= 1) ? g_G : (MODE == 2 ? g_Edge : g_qt);

    __shared__ __align__(16) float As[16][132];
    __shared__ __align__(16) float Bs[16][132];

    const int tid = threadIdx.x;
    const int tx = tid & 15, ty = tid >> 4;

    unsigned long long acc[8][4];
#pragma unroll
    for (int i = 0; i < 8; i++)
#pragma unroll
        for (int j = 0; j < 4; j++) acc[i][j] = 0ull;

    for (int kk = 0; kk < K; kk += 16) {
#pragma unroll
        for (int i = 0; i < 2; i++) {
            int idx = tid + i * 256;
            int m = idx >> 2, k = (idx & 3) * 4;
            float4 v = *(const float4*)(A + (size_t)(row0 + m) * lda + kk + k);
            As[k + 0][m] = v.x; As[k + 1][m] = v.y; As[k + 2][m] = v.z; As[k + 3][m] = v.w;
        }
#pragma unroll
        for (int i = 0; i < 2; i++) {
            int idx = tid + i * 256;
            int n = idx >> 2, k = (idx & 3) * 4;
            int gk = kk + k;
            const float* Wp = W0; int lk = gk;
            if (MODE <= 1) { if (gk >= 256) { Wp = W1; lk = gk - 256; } }
            float4 v = *(const float4*)(Wp + (size_t)(col0 + n) * 256 + lk);
            Bs[k + 0][n] = v.x; Bs[k + 1][n] = v.y; Bs[k + 2][n] = v.z; Bs[k + 3][n] = v.w;
        }
        __syncthreads();
#pragma unroll
        for (int p = 0; p < 16; p++) {
            float4 a0 = *(const float4*)&As[p][ty * 8];
            float4 a1 = *(const float4*)&As[p][ty * 8 + 4];
            float4 b0 = *(const float4*)&Bs[p][tx * 8];
            float4 b1 = *(const float4*)&Bs[p][tx * 8 + 4];
            unsigned long long bb[4];
            bb[0] = pack2(b0.x, b0.y); bb[1] = pack2(b0.z, b0.w);
            bb[2] = pack2(b1.x, b1.y); bb[3] = pack2(b1.z, b1.w);
            float av[8] = {a0.x, a0.y, a0.z, a0.w, a1.x, a1.y, a1.z, a1.w};
#pragma unroll
            for (int i = 0; i < 8; i++) {
                unsigned long long aa = pack2(av[i], av[i]);
#pragma unroll
                for (int j = 0; j < 4; j++) FMA2(acc[i][j], aa, bb[j]);
            }
        }
        __syncthreads();
    }

    // epilogue
#pragma unroll
    for (int i = 0; i < 8; i++) {
        int r = row0 + ty * 8 + i;
        float c[8];
#pragma unroll
        for (int j = 0; j < 4; j++) {
            float2 f = unpack2(acc[i][j]);
            c[2 * j] = f.x; c[2 * j + 1] = f.y;
        }
        if (MODE <= 1) {
            bool ok = (MODE == 0) ? (r < bound) : (r >= bound);
            if (ok) {
                int bt = g_rmap[r];
                float* o = g_Edge + (size_t)bt * 256 + col0 + tx * 8;
                *(float4*)(o)     = make_float4(c[0], c[1], c[2], c[3]);
                *(float4*)(o + 4) = make_float4(c[4], c[5], c[6], c[7]);
            }
        } else if (MODE == 2) {
            float* o = g_S + (size_t)r * 256 + col0 + tx * 8;
            *(float4*)(o)     = make_float4(c[0], c[1], c[2], c[3]);
            *(float4*)(o + 4) = make_float4(c[4], c[5], c[6], c[7]);
        } else {
            const float* bi = bias + col0 + tx * 8;
#pragma unroll
            for (int j = 0; j < 8; j++) c[j] += bi[j];
            float* o = g_inp + (size_t)r * 256 + col0 + tx * 8;
            *(float4*)(o)     = make_float4(c[0], c[1], c[2], c[3]);
            *(float4*)(o + 4) = make_float4(c[4], c[5], c[6], c[7]);
        }
    }
}

// qt = relu(edge_4 + max(0, max_{t=0..4} S_t))
__global__ void k_qt() {
    int i = blockIdx.x * blockDim.x + threadIdx.x;
    if (i >= Bb * Hh) return;
    int b = i >> 8, h = i & 255;
    float m = 0.f;
#pragma unroll
    for (int t = 0; t < 5; t++) m = fmaxf(m, g_S[(size_t)(b * 5 + t) * 256 + h]);
    float q = g_Edge[(size_t)(b * 5 + 4) * 256 + h] + m;
    g_qt[i] = fmaxf(q, 0.f);
}

// ctx GEMM (M=229376, K=256, N=256 in one block-col) fused with
// att2[m] = 10*tanh( mask[m] ? sum_h V[h]*tanh(inp[b,h] + gemm + b_ctx[h]) : -1e9 )
__global__ void __launch_bounds__(256) sgemm_ctx(const float* __restrict__ A,
                                                 const float* __restrict__ W,
                                                 const float* __restrict__ bias,
                                                 const float* __restrict__ Vv,
                                                 const int* __restrict__ mask) {
    const int row0 = blockIdx.x * 64;
    __shared__ __align__(16) float As[16][68];
    __shared__ __align__(16) float Bs[16][260];
    const int tid = threadIdx.x;
    const int lane = tid & 31, w = tid >> 5;

    unsigned long long acc[8][4];
#pragma unroll
    for (int i = 0; i < 8; i++)
#pragma unroll
        for (int j = 0; j < 4; j++) acc[i][j] = 0ull;

    for (int kk = 0; kk < 256; kk += 16) {
        {
            int idx = tid;
            int m = idx >> 2, k = (idx & 3) * 4;
            float4 v = *(const float4*)(A + (size_t)(row0 + m) * 256 + kk + k);
            As[k + 0][m] = v.x; As[k + 1][m] = v.y; As[k + 2][m] = v.z; As[k + 3][m] = v.w;
        }
#pragma unroll
        for (int i = 0; i < 4; i++) {
            int idx = tid + i * 256;
            int n = idx >> 2, k = (idx & 3) * 4;
            float4 v = *(const float4*)(W + (size_t)n * 256 + kk + k);
            Bs[k + 0][n] = v.x; Bs[k + 1][n] = v.y; Bs[k + 2][n] = v.z; Bs[k + 3][n] = v.w;
        }
        __syncthreads();
#pragma unroll
        for (int p = 0; p < 16; p++) {
            float4 a0 = *(const float4*)&As[p][w * 8];
            float4 a1 = *(const float4*)&As[p][w * 8 + 4];
            float4 b0 = *(const float4*)&Bs[p][lane * 8];
            float4 b1 = *(const float4*)&Bs[p][lane * 8 + 4];
            unsigned long long bb[4];
            bb[0] = pack2(b0.x, b0.y); bb[1] = pack2(b0.z, b0.w);
            bb[2] = pack2(b1.x, b1.y); bb[3] = pack2(b1.z, b1.w);
            float av[8] = {a0.x, a0.y, a0.z, a0.w, a1.x, a1.y, a1.z, a1.w};
#pragma unroll
            for (int i = 0; i < 8; i++) {
                unsigned long long aa = pack2(av[i], av[i]);
#pragma unroll
                for (int j = 0; j < 4; j++) FMA2(acc[i][j], aa, bb[j]);
            }
        }
        __syncthreads();
    }

    float bc[8], vv[8];
#pragma unroll
    for (int j = 0; j < 8; j++) { bc[j] = bias[lane * 8 + j]; vv[j] = Vv[lane * 8 + j]; }

#pragma unroll
    for (int i = 0; i < 8; i++) {
        int m = row0 + w * 8 + i;
        int b = m / Ll;
        const float* ip = g_inp + (size_t)b * 256 + lane * 8;
        float s = 0.f;
#pragma unroll
        for (int j = 0; j < 4; j++) {
            float2 cf = unpack2(acc[i][j]);
            int jj = 2 * j;
            s += vv[jj]     * tanhf(ip[jj]     + (cf.x + bc[jj]));
            s += vv[jj + 1] * tanhf(ip[jj + 1] + (cf.y + bc[jj + 1]));
        }
#pragma unroll
        for (int o = 16; o > 0; o >>= 1) s += __shfl_xor_sync(0xffffffffu, s, o);
        if (lane == 0) {
            if (mask[m] == 0) s = -1000000000.0f;
            g_att2[m] = 10.0f * tanhf(s);
        }
    }
}

// per-column (l) softmax stats over batch axis
__global__ void k_colred() {
    const int l = blockIdx.x;
    __shared__ float red[256];
    float mx = __int_as_float(0xff800000);  // -inf
    for (int b = threadIdx.x; b < Bb; b += 256) mx = fmaxf(mx, g_att2[b * Ll + l]);
    red[threadIdx.x] = mx; __syncthreads();
    for (int o = 128; o > 0; o >>= 1) {
        if (threadIdx.x < o) red[threadIdx.x] = fmaxf(red[threadIdx.x], red[threadIdx.x + o]);
        __syncthreads();
    }
    mx = red[0]; __syncthreads();
    float sum = 0.f;
    for (int b = threadIdx.x; b < Bb; b += 256) sum += expf(g_att2[b * Ll + l] - mx);
    red[threadIdx.x] = sum; __syncthreads();
    for (int o = 128; o > 0; o >>= 1) {
        if (threadIdx.x < o) red[threadIdx.x] += red[threadIdx.x + o];
        __syncthreads();
    }
    if (threadIdx.x == 0) {
        g_colmax[l] = mx;
        g_colsum[l] = red[0];
        g_logZ[l]   = mx + logf(red[0]);
    }
}

// Gumbel-argmax (JAX categorical, key 42) + p + new_mask; writes full output
__global__ void k_final(const int* __restrict__ mask, float* __restrict__ out) {
    int b = blockIdx.x * blockDim.x + threadIdx.x;
    if (b >= Bb) return;
    const float TINY = 1.17549435e-38f;
    float best = __int_as_float(0xff800000);
    int idx = 0;
    float a2[Ll];
#pragma unroll
    for (int l = 0; l < Ll; l++) {
        float a = g_att2[b * Ll + l];
        a2[l] = a;
        float la = a - g_logZ[l];
        uint32_t bits = jax_bits((uint32_t)(b * Ll + l));
        float fl = __uint_as_float((bits >> 9) | 0x3F800000u) - 1.0f;
        float u  = fmaxf(TINY, fl + TINY);
        float g  = -logf(-logf(u));
        float s  = la + g;
        if (s > best) { best = s; idx = l; }
    }
    float p = expf(a2[idx] - g_colmax[idx]) / g_colsum[idx];
    out[b]      = (float)idx;
    out[Bb + b] = p;
#pragma unroll
    for (int l = 0; l < Ll; l++)
        out[2 * Bb + b * Ll + l] = (float)(mask[b * Ll + l] - (l == idx ? 1 : 0));
}

// ---------------- launcher ----------------
extern "C" void kernel_launch(void* const* d_in, const int* in_sizes, int n_in,
                              void* d_out, int out_size) {
    const float* enc    = (const float*)d_in[0];
    const int*   xes    = (const int*)  d_in[1];   // int32 or int64 (auto-detected)
    const int*   mask   = (const int*)  d_in[2];
    const float* W_h    = (const float*)d_in[3];
    const float* W_v    = (const float*)d_in[4];
    const float* Ws_h   = (const float*)d_in[5];
    const float* Ws_v   = (const float*)d_in[6];
    const float* W_edge = (const float*)d_in[7];
    const float* W_in   = (const float*)d_in[8];
    const float* b_in   = (const float*)d_in[9];
    const float* W_ctx  = (const float*)d_in[10];
    const float* b_ctx  = (const float*)d_in[11];
    const float* Vv     = (const float*)d_in[12];
    float* out = (float*)d_out;

    k_init<<<1, 1>>>();
    k_detect<<<1, 128>>>(xes);
    k_map<<<(MROWS + 255) / 256, 256>>>(xes);
    k_gather<<<(MROWS * 128) / 256, 256>>>(enc);

    dim3 gE(MROWS / 128, 2);
    sgemm128<0><<<gE, 256>>>(W_h, W_v, nullptr);        // cond partition
    sgemm128<1><<<gE, 256>>>(Ws_h, Ws_v, nullptr);      // else partition
    sgemm128<2><<<gE, 256>>>(W_edge, W_edge, nullptr);  // S = Edge @ W_edge^T
    k_qt<<<(Bb * Hh) / 256, 256>>>();
    sgemm128<3><<<dim3(Bb / 128, 2), 256>>>(W_in, W_in, b_in);  // inp
    sgemm_ctx<<<MCTX / 64, 256>>>(enc, W_ctx, b_ctx, Vv, mask);
    k_colred<<<Ll, 256>>>();
    k_final<<<(Bb + 255) / 256, 256>>>(mask, out);
}

// round 7
// speedup vs baseline: 1.0673x; 1.0673x over previous
#include <cuda_runtime.h>
#include <stdint.h>

// Problem constants
#define Bb    32768
#define Ll    7
#define Tt    6
#define Hh    256
#define TS    5                 // only edges t=0..4 are live
#define MROWS (Bb * TS)         // 163840
#define MCTX  (Bb * Ll)         // 229376

#define PRNG_MODE 1             // partitionable threefry, o0^o1 fold (verified R6)

// ---------------- device scratch (static, allocation-free) ----------------
__device__ float g_Edge[(size_t)MROWS * Hh];    // edge rows, natural bt = b*5+t order
__device__ float g_qt  [Bb * Hh];
__device__ float g_inp [Bb * Hh];
__device__ float g_att2[MCTX];
__device__ float g_colmax[Ll];
__device__ float g_colsum[Ll];
__device__ float g_logZ[Ll];
__device__ int   g_rmap[MROWS];   // packed GEMM row -> bt
__device__ int   g_hv  [MROWS];   // packed h | v<<8
__device__ int   g_cntA;          // rows with cond (t==0)
__device__ int   g_cntB;
__device__ int   g_is64;          // xes dtype flag

// ---------------- small helpers ----------------
__device__ __forceinline__ unsigned long long pack2(float x, float y) {
    unsigned long long r;
    asm("mov.b64 %0, {%1, %2};" : "=l"(r) : "r"(__float_as_uint(x)), "r"(__float_as_uint(y)));
    return r;
}
__device__ __forceinline__ float2 unpack2(unsigned long long v) {
    unsigned int lo, hi;
    asm("mov.b64 {%0, %1}, %2;" : "=r"(lo), "=r"(hi) : "l"(v));
    float2 f; f.x = __uint_as_float(lo); f.y = __uint_as_float(hi); return f;
}
#define FMA2(acc, a, b) asm("fma.rn.f32x2 %0, %1, %2, %0;" : "+l"(acc) : "l"(a), "l"(b))

__device__ __forceinline__ uint32_t rotl32(uint32_t v, int r) { return (v << r) | (v >> (32 - r)); }

// JAX Threefry-2x32-20, key = (0, 42)
__device__ __forceinline__ void tf2x32(uint32_t x0, uint32_t x1, uint32_t& o0, uint32_t& o1) {
    const uint32_t k0 = 0u, k1 = 42u, k2 = 0u ^ 42u ^ 0x1BD11BDAu;
    x0 += k0; x1 += k1;
#define TFR(r) { x0 += x1; x1 = rotl32(x1, (r)); x1 ^= x0; }
    TFR(13) TFR(15) TFR(26) TFR(6)   x0 += k1; x1 += k2 + 1u;
    TFR(17) TFR(29) TFR(16) TFR(24)  x0 += k2; x1 += k0 + 2u;
    TFR(13) TFR(15) TFR(26) TFR(6)   x0 += k0; x1 += k1 + 3u;
    TFR(17) TFR(29) TFR(16) TFR(24)  x0 += k1; x1 += k2 + 4u;
    TFR(13) TFR(15) TFR(26) TFR(6)   x0 += k2; x1 += k0 + 5u;
#undef TFR
    o0 = x0; o1 = x1;
}

__device__ __forceinline__ uint32_t jax_bits(uint32_t n) {
    uint32_t o0, o1; tf2x32(0u, n, o0, o1);
#if PRNG_MODE == 1
    return o0 ^ o1;
#else
    return o1;
#endif
}

// ---------------- setup kernels ----------------
__global__ void k_init() { g_cntA = 0; g_cntB = 0; }

__global__ void k_detect(const int* __restrict__ xes) {
    __shared__ int any;
    if (threadIdx.x == 0) any = 0;
    __syncthreads();
    if (xes[2 * threadIdx.x + 1] != 0) any = 1;
    __syncthreads();
    if (threadIdx.x == 0) g_is64 = !any;
}

__global__ void k_map(const int* __restrict__ xes) {
    int bt = blockIdx.x * blockDim.x + threadIdx.x;
    if (bt >= MROWS) return;
    int b = bt / TS, t = bt - b * TS;
    int base = (b * Tt + t) * 3;
    int s = g_is64 ? 2 : 1;
    int h  = xes[(base + 0) * s];
    int v  = xes[(base + 1) * s];
    int tt = xes[(base + 2) * s];
    int g;
    if (tt == 0) g = atomicAdd(&g_cntA, 1);
    else         g = MROWS - 1 - atomicAdd(&g_cntB, 1);
    g_rmap[g] = bt;
    g_hv[g]   = h | (v << 8);
}

// ---------------- edge GEMM: fused gather, merged partitions, pipelined ----
// 128 rows x 256 cols per block, 512 threads, K = 512 (h half then v half).
__global__ void __launch_bounds__(512) k_edges(const float* __restrict__ enc,
                                               const float* __restrict__ Wh,
                                               const float* __restrict__ Wv,
                                               const float* __restrict__ Wsh,
                                               const float* __restrict__ Wsv) {
    const int row0 = blockIdx.x * 128;
    __shared__ __align__(16) float As[16][132];
    __shared__ __align__(16) float Bs[16][260];
    __shared__ const float* rpH[128];
    __shared__ const float* rpV[128];
    __shared__ int sbt[128];

    const int tid = threadIdx.x;
    if (tid < 128) {
        int g = row0 + tid;
        int bt = g_rmap[g];
        int hv = g_hv[g];
        int b = bt / TS;
        sbt[tid] = bt;
        rpH[tid] = enc + (size_t)(b * Ll + (hv & 255)) * 256;
        rpV[tid] = enc + (size_t)(b * Ll + (hv >> 8)) * 256;
    }
    __syncthreads();

    const int bound = g_cntA;
    const int tx = tid & 31, ty = tid >> 5;     // tx: 8 cols each (256), ty: 8 rows each (128)
    const int am = tid >> 2, ak = (tid & 3) * 4; // A/B load mapping (am in 0..127)

    for (int pass = 0; pass < 2; pass++) {
        if (pass == 0 && row0 >= bound) continue;
        if (pass == 1 && row0 + 128 <= bound) continue;
        const float* WA = pass ? Wsh : Wh;
        const float* WB = pass ? Wsv : Wv;

        unsigned long long acc[8][4];
#pragma unroll
        for (int i = 0; i < 8; i++)
#pragma unroll
            for (int j = 0; j < 4; j++) acc[i][j] = 0ull;

        // preload kk = 0
        float4 a_st = *(const float4*)(rpH[am] + ak);
        float4 b_st0 = *(const float4*)(WA + (size_t)am * 256 + ak);
        float4 b_st1 = *(const float4*)(WA + (size_t)(am + 128) * 256 + ak);

        for (int kk = 0; kk < 512; kk += 16) {
            __syncthreads();
            As[ak + 0][am] = a_st.x; As[ak + 1][am] = a_st.y;
            As[ak + 2][am] = a_st.z; As[ak + 3][am] = a_st.w;
            Bs[ak + 0][am] = b_st0.x; Bs[ak + 1][am] = b_st0.y;
            Bs[ak + 2][am] = b_st0.z; Bs[ak + 3][am] = b_st0.w;
            Bs[ak + 0][am + 128] = b_st1.x; Bs[ak + 1][am + 128] = b_st1.y;
            Bs[ak + 2][am + 128] = b_st1.z; Bs[ak + 3][am + 128] = b_st1.w;
            __syncthreads();

            int kn = kk + 16;
            if (kn < 512) {
                const float* rp = (kn < 256) ? rpH[am] : rpV[am];
                int off = (kn & 255) + ak;
                a_st = *(const float4*)(rp + off);
                const float* Wp = (kn < 256) ? WA : WB;
                b_st0 = *(const float4*)(Wp + (size_t)am * 256 + off);
                b_st1 = *(const float4*)(Wp + (size_t)(am + 128) * 256 + off);
            }

#pragma unroll
            for (int p = 0; p < 16; p++) {
                float4 a0 = *(const float4*)&As[p][ty * 8];
                float4 a1 = *(const float4*)&As[p][ty * 8 + 4];
                float4 b0 = *(const float4*)&Bs[p][tx * 8];
                float4 b1 = *(const float4*)&Bs[p][tx * 8 + 4];
                unsigned long long bb[4];
                bb[0] = pack2(b0.x, b0.y); bb[1] = pack2(b0.z, b0.w);
                bb[2] = pack2(b1.x, b1.y); bb[3] = pack2(b1.z, b1.w);
                float av[8] = {a0.x, a0.y, a0.z, a0.w, a1.x, a1.y, a1.z, a1.w};
#pragma unroll
                for (int i = 0; i < 8; i++) {
                    unsigned long long aa = pack2(av[i], av[i]);
#pragma unroll
                    for (int j = 0; j < 4; j++) FMA2(acc[i][j], aa, bb[j]);
                }
            }
        }

#pragma unroll
        for (int i = 0; i < 8; i++) {
            int r = ty * 8 + i;
            int g = row0 + r;
            bool ok = (pass == 0) ? (g < bound) : (g >= bound);
            if (ok) {
                float c[8];
#pragma unroll
                for (int j = 0; j < 4; j++) {
                    float2 f = unpack2(acc[i][j]);
                    c[2 * j] = f.x; c[2 * j + 1] = f.y;
                }
                float* o = g_Edge + (size_t)sbt[r] * 256 + tx * 8;
                *(float4*)(o)     = make_float4(c[0], c[1], c[2], c[3]);
                *(float4*)(o + 4) = make_float4(c[4], c[5], c[6], c[7]);
            }
        }
    }
}

// ---------------- S GEMM fused with subtree-max + qt ----------------------
// 160 rows (32 b's x 5 t's) x 128 cols, 256 threads. Each thread's 10-row
// microtile = exactly 2 complete b-groups -> thread-local max reduction.
// qt[b,c] = relu(Edge[b*5+4,c] + max(0, max_t S[b*5+t,c]))
__global__ void __launch_bounds__(256) k_subq(const float* __restrict__ We) {
    const int row0 = blockIdx.x * 160;
    const int col0 = blockIdx.y * 128;
    __shared__ __align__(16) float As[16][164];
    __shared__ __align__(16) float Bs[16][132];
    const int tid = threadIdx.x;
    const int tx = tid & 15, ty = tid >> 4;   // tx: 8 cols (128), ty: 10 rows (160)

    unsigned long long acc[10][4];
#pragma unroll
    for (int i = 0; i < 10; i++)
#pragma unroll
        for (int j = 0; j < 4; j++) acc[i][j] = 0ull;

    float4 a_st[3], b_st[2];
    // preload kk = 0
#pragma unroll
    for (int i = 0; i < 3; i++) {
        int idx = tid + i * 256;
        if (idx < 640) {
            int m = idx >> 2, kq = (idx & 3) * 4;
            a_st[i] = *(const float4*)(g_Edge + (size_t)(row0 + m) * 256 + kq);
        }
    }
#pragma unroll
    for (int i = 0; i < 2; i++) {
        int idx = tid + i * 256;
        int n = idx >> 2, kq = (idx & 3) * 4;
        b_st[i] = *(const float4*)(We + (size_t)(col0 + n) * 256 + kq);
    }

    for (int kk = 0; kk < 256; kk += 16) {
        __syncthreads();
#pragma unroll
        for (int i = 0; i < 3; i++) {
            int idx = tid + i * 256;
            if (idx < 640) {
                int m = idx >> 2, kq = (idx & 3) * 4;
                As[kq + 0][m] = a_st[i].x; As[kq + 1][m] = a_st[i].y;
                As[kq + 2][m] = a_st[i].z; As[kq + 3][m] = a_st[i].w;
            }
        }
#pragma unroll
        for (int i = 0; i < 2; i++) {
            int idx = tid + i * 256;
            int n = idx >> 2, kq = (idx & 3) * 4;
            Bs[kq + 0][n] = b_st[i].x; Bs[kq + 1][n] = b_st[i].y;
            Bs[kq + 2][n] = b_st[i].z; Bs[kq + 3][n] = b_st[i].w;
        }
        __syncthreads();

        int kn = kk + 16;
        if (kn < 256) {
#pragma unroll
            for (int i = 0; i < 3; i++) {
                int idx = tid + i * 256;
                if (idx < 640) {
                    int m = idx >> 2, kq = (idx & 3) * 4;
                    a_st[i] = *(const float4*)(g_Edge + (size_t)(row0 + m) * 256 + kn + kq);
                }
            }
#pragma unroll
            for (int i = 0; i < 2; i++) {
                int idx = tid + i * 256;
                int n = idx >> 2, kq = (idx & 3) * 4;
                b_st[i] = *(const float4*)(We + (size_t)(col0 + n) * 256 + kn + kq);
            }
        }

#pragma unroll
        for (int p = 0; p < 16; p++) {
            float av[10];
#pragma unroll
            for (int i = 0; i < 10; i += 2) {
                float2 t2 = *(const float2*)&As[p][ty * 10 + i];
                av[i] = t2.x; av[i + 1] = t2.y;
            }
            float4 b0 = *(const float4*)&Bs[p][tx * 8];
            float4 b1 = *(const float4*)&Bs[p][tx * 8 + 4];
            unsigned long long bb[4];
            bb[0] = pack2(b0.x, b0.y); bb[1] = pack2(b0.z, b0.w);
            bb[2] = pack2(b1.x, b1.y); bb[3] = pack2(b1.z, b1.w);
#pragma unroll
            for (int i = 0; i < 10; i++) {
                unsigned long long aa = pack2(av[i], av[i]);
#pragma unroll
                for (int j = 0; j < 4; j++) FMA2(acc[i][j], aa, bb[j]);
            }
        }
    }

    // epilogue: two b-groups per thread
#pragma unroll
    for (int grp = 0; grp < 2; grp++) {
        int gr = row0 + ty * 10 + grp * 5;    // = b*5
        int b = gr / 5;
        float mx[8];
#pragma unroll
        for (int c = 0; c < 8; c++) mx[c] = 0.f;
#pragma unroll
        for (int i = 0; i < 5; i++) {
#pragma unroll
            for (int j = 0; j < 4; j++) {
                float2 f = unpack2(acc[grp * 5 + i][j]);
                mx[2 * j]     = fmaxf(mx[2 * j],     f.x);
                mx[2 * j + 1] = fmaxf(mx[2 * j + 1], f.y);
            }
        }
        const float* e4 = g_Edge + (size_t)(gr + 4) * 256 + col0 + tx * 8;
        float4 e0 = *(const float4*)(e4);
        float4 e1 = *(const float4*)(e4 + 4);
        float q[8];
        q[0] = fmaxf(e0.x + mx[0], 0.f); q[1] = fmaxf(e0.y + mx[1], 0.f);
        q[2] = fmaxf(e0.z + mx[2], 0.f); q[3] = fmaxf(e0.w + mx[3], 0.f);
        q[4] = fmaxf(e1.x + mx[4], 0.f); q[5] = fmaxf(e1.y + mx[5], 0.f);
        q[6] = fmaxf(e1.z + mx[6], 0.f); q[7] = fmaxf(e1.w + mx[7], 0.f);
        float* o = g_qt + (size_t)b * 256 + col0 + tx * 8;
        *(float4*)(o)     = make_float4(q[0], q[1], q[2], q[3]);
        *(float4*)(o + 4) = make_float4(q[4], q[5], q[6], q[7]);
    }
}

// ---------------- inp = qt @ W_in^T + b_in (pipelined 128x128) ------------
__global__ void __launch_bounds__(256) k_inp(const float* __restrict__ Wi,
                                             const float* __restrict__ bi) {
    const int row0 = blockIdx.x * 128;
    const int col0 = blockIdx.y * 128;
    __shared__ __align__(16) float As[16][132];
    __shared__ __align__(16) float Bs[16][132];
    const int tid = threadIdx.x;
    const int tx = tid & 15, ty = tid >> 4;

    unsigned long long acc[8][4];
#pragma unroll
    for (int i = 0; i < 8; i++)
#pragma unroll
        for (int j = 0; j < 4; j++) acc[i][j] = 0ull;

    float4 a_st[2], b_st[2];
#pragma unroll
    for (int i = 0; i < 2; i++) {
        int idx = tid + i * 256;
        int m = idx >> 2, kq = (idx & 3) * 4;
        a_st[i] = *(const float4*)(g_qt + (size_t)(row0 + m) * 256 + kq);
        b_st[i] = *(const float4*)(Wi + (size_t)(col0 + m) * 256 + kq);
    }

    for (int kk = 0; kk < 256; kk += 16) {
        __syncthreads();
#pragma unroll
        for (int i = 0; i < 2; i++) {
            int idx = tid + i * 256;
            int m = idx >> 2, kq = (idx & 3) * 4;
            As[kq + 0][m] = a_st[i].x; As[kq + 1][m] = a_st[i].y;
            As[kq + 2][m] = a_st[i].z; As[kq + 3][m] = a_st[i].w;
            Bs[kq + 0][m] = b_st[i].x; Bs[kq + 1][m] = b_st[i].y;
            Bs[kq + 2][m] = b_st[i].z; Bs[kq + 3][m] = b_st[i].w;
        }
        __syncthreads();

        int kn = kk + 16;
        if (kn < 256) {
#pragma unroll
            for (int i = 0; i < 2; i++) {
                int idx = tid + i * 256;
                int m = idx >> 2, kq = (idx & 3) * 4;
                a_st[i] = *(const float4*)(g_qt + (size_t)(row0 + m) * 256 + kn + kq);
                b_st[i] = *(const float4*)(Wi + (size_t)(col0 + m) * 256 + kn + kq);
            }
        }

#pragma unroll
        for (int p = 0; p < 16; p++) {
            float4 a0 = *(const float4*)&As[p][ty * 8];
            float4 a1 = *(const float4*)&As[p][ty * 8 + 4];
            float4 b0 = *(const float4*)&Bs[p][tx * 8];
            float4 b1 = *(const float4*)&Bs[p][tx * 8 + 4];
            unsigned long long bb[4];
            bb[0] = pack2(b0.x, b0.y); bb[1] = pack2(b0.z, b0.w);
            bb[2] = pack2(b1.x, b1.y); bb[3] = pack2(b1.z, b1.w);
            float av[8] = {a0.x, a0.y, a0.z, a0.w, a1.x, a1.y, a1.z, a1.w};
#pragma unroll
            for (int i = 0; i < 8; i++) {
                unsigned long long aa = pack2(av[i], av[i]);
#pragma unroll
                for (int j = 0; j < 4; j++) FMA2(acc[i][j], aa, bb[j]);
            }
        }
    }

#pragma unroll
    for (int i = 0; i < 8; i++) {
        int r = row0 + ty * 8 + i;
        float c[8];
#pragma unroll
        for (int j = 0; j < 4; j++) {
            float2 f = unpack2(acc[i][j]);
            c[2 * j] = f.x; c[2 * j + 1] = f.y;
        }
        const float* bp = bi + col0 + tx * 8;
#pragma unroll
        for (int j = 0; j < 8; j++) c[j] += bp[j];
        float* o = g_inp + (size_t)r * 256 + col0 + tx * 8;
        *(float4*)(o)     = make_float4(c[0], c[1], c[2], c[3]);
        *(float4*)(o + 4) = make_float4(c[4], c[5], c[6], c[7]);
    }
}

// ---------------- ctx GEMM fused with att2 (pipelined 64x256) -------------
__global__ void __launch_bounds__(256) k_ctx(const float* __restrict__ A,
                                             const float* __restrict__ W,
                                             const float* __restrict__ bias,
                                             const float* __restrict__ Vv,
                                             const int* __restrict__ mask) {
    const int row0 = blockIdx.x * 64;
    __shared__ __align__(16) float As[16][68];
    __shared__ __align__(16) float Bs[16][260];
    const int tid = threadIdx.x;
    const int lane = tid & 31, w = tid >> 5;

    unsigned long long acc[8][4];
#pragma unroll
    for (int i = 0; i < 8; i++)
#pragma unroll
        for (int j = 0; j < 4; j++) acc[i][j] = 0ull;

    const int am = tid >> 2, ak = (tid & 3) * 4;  // am in 0..63 for A
    float4 a_st = *(const float4*)(A + (size_t)(row0 + am) * 256 + ak);
    float4 b_st[4];
#pragma unroll
    for (int i = 0; i < 4; i++)
        b_st[i] = *(const float4*)(W + (size_t)(am + i * 64) * 256 + ak);

    for (int kk = 0; kk < 256; kk += 16) {
        __syncthreads();
        As[ak + 0][am] = a_st.x; As[ak + 1][am] = a_st.y;
        As[ak + 2][am] = a_st.z; As[ak + 3][am] = a_st.w;
#pragma unroll
        for (int i = 0; i < 4; i++) {
            int n = am + i * 64;
            Bs[ak + 0][n] = b_st[i].x; Bs[ak + 1][n] = b_st[i].y;
            Bs[ak + 2][n] = b_st[i].z; Bs[ak + 3][n] = b_st[i].w;
        }
        __syncthreads();

        int kn = kk + 16;
        if (kn < 256) {
            a_st = *(const float4*)(A + (size_t)(row0 + am) * 256 + kn + ak);
#pragma unroll
            for (int i = 0; i < 4; i++)
                b_st[i] = *(const float4*)(W + (size_t)(am + i * 64) * 256 + kn + ak);
        }

#pragma unroll
        for (int p = 0; p < 16; p++) {
            float4 a0 = *(const float4*)&As[p][w * 8];
            float4 a1 = *(const float4*)&As[p][w * 8 + 4];
            float4 b0 = *(const float4*)&Bs[p][lane * 8];
            float4 b1 = *(const float4*)&Bs[p][lane * 8 + 4];
            unsigned long long bb[4];
            bb[0] = pack2(b0.x, b0.y); bb[1] = pack2(b0.z, b0.w);
            bb[2] = pack2(b1.x, b1.y); bb[3] = pack2(b1.z, b1.w);
            float av[8] = {a0.x, a0.y, a0.z, a0.w, a1.x, a1.y, a1.z, a1.w};
#pragma unroll
            for (int i = 0; i < 8; i++) {
                unsigned long long aa = pack2(av[i], av[i]);
#pragma unroll
                for (int j = 0; j < 4; j++) FMA2(acc[i][j], aa, bb[j]);
            }
        }
    }

    float bc[8], vv[8];
#pragma unroll
    for (int j = 0; j < 8; j++) { bc[j] = bias[lane * 8 + j]; vv[j] = Vv[lane * 8 + j]; }

#pragma unroll
    for (int i = 0; i < 8; i++) {
        int m = row0 + w * 8 + i;
        int b = m / Ll;
        const float* ip = g_inp + (size_t)b * 256 + lane * 8;
        float s = 0.f;
#pragma unroll
        for (int j = 0; j < 4; j++) {
            float2 cf = unpack2(acc[i][j]);
            int jj = 2 * j;
            s += vv[jj]     * tanhf(ip[jj]     + (cf.x + bc[jj]));
            s += vv[jj + 1] * tanhf(ip[jj + 1] + (cf.y + bc[jj + 1]));
        }
#pragma unroll
        for (int o = 16; o > 0; o >>= 1) s += __shfl_xor_sync(0xffffffffu, s, o);
        if (lane == 0) {
            if (mask[m] == 0) s = -1000000000.0f;
            g_att2[m] = 10.0f * tanhf(s);
        }
    }
}

// ---------------- per-column softmax stats over batch axis ----------------
__global__ void k_colred() {
    const int l = blockIdx.x;
    __shared__ float red[256];
    float mx = __int_as_float(0xff800000);
    for (int b = threadIdx.x; b < Bb; b += 256) mx = fmaxf(mx, g_att2[b * Ll + l]);
    red[threadIdx.x] = mx; __syncthreads();
    for (int o = 128; o > 0; o >>= 1) {
        if (threadIdx.x < o) red[threadIdx.x] = fmaxf(red[threadIdx.x], red[threadIdx.x + o]);
        __syncthreads();
    }
    mx = red[0]; __syncthreads();
    float sum = 0.f;
    for (int b = threadIdx.x; b < Bb; b += 256) sum += expf(g_att2[b * Ll + l] - mx);
    red[threadIdx.x] = sum; __syncthreads();
    for (int o = 128; o > 0; o >>= 1) {
        if (threadIdx.x < o) red[threadIdx.x] += red[threadIdx.x + o];
        __syncthreads();
    }
    if (threadIdx.x == 0) {
        g_colmax[l] = mx;
        g_colsum[l] = red[0];
        g_logZ[l]   = mx + logf(red[0]);
    }
}

// ---------------- Gumbel-argmax + p + new_mask ----------------------------
__global__ void k_final(const int* __restrict__ mask, float* __restrict__ out) {
    int b = blockIdx.x * blockDim.x + threadIdx.x;
    if (b >= Bb) return;
    const float TINY = 1.17549435e-38f;
    float best = __int_as_float(0xff800000);
    int idx = 0;
    float a2[Ll];
#pragma unroll
    for (int l = 0; l < Ll; l++) {
        float a = g_att2[b * Ll + l];
        a2[l] = a;
        float la = a - g_logZ[l];
        uint32_t bits = jax_bits((uint32_t)(b * Ll + l));
        float fl = __uint_as_float((bits >> 9) | 0x3F800000u) - 1.0f;
        float u  = fmaxf(TINY, fl + TINY);
        float g  = -logf(-logf(u));
        float s  = la + g;
        if (s > best) { best = s; idx = l; }
    }
    float p = expf(a2[idx] - g_colmax[idx]) / g_colsum[idx];
    out[b]      = (float)idx;
    out[Bb + b] = p;
#pragma unroll
    for (int l = 0; l < Ll; l++)
        out[2 * Bb + b * Ll + l] = (float)(mask[b * Ll + l] - (l == idx ? 1 : 0));
}

// ---------------- launcher ----------------
extern "C" void kernel_launch(void* const* d_in, const int* in_sizes, int n_in,
                              void* d_out, int out_size) {
    const float* enc    = (const float*)d_in[0];
    const int*   xes    = (const int*)  d_in[1];
    const int*   mask   = (const int*)  d_in[2];
    const float* W_h    = (const float*)d_in[3];
    const float* W_v    = (const float*)d_in[4];
    const float* Ws_h   = (const float*)d_in[5];
    const float* Ws_v   = (const float*)d_in[6];
    const float* W_edge = (const float*)d_in[7];
    const float* W_in   = (const float*)d_in[8];
    const float* b_in   = (const float*)d_in[9];
    const float* W_ctx  = (const float*)d_in[10];
    const float* b_ctx  = (const float*)d_in[11];
    const float* Vv     = (const float*)d_in[12];
    float* out = (float*)d_out;

    k_init<<<1, 1>>>();
    k_detect<<<1, 128>>>(xes);
    k_map<<<(MROWS + 255) / 256, 256>>>(xes);

    k_edges<<<MROWS / 128, 512>>>(enc, W_h, W_v, Ws_h, Ws_v);   // gather fused
    k_subq<<<dim3(MROWS / 160, 2), 256>>>(W_edge);              // S + max + qt fused
    k_inp<<<dim3(Bb / 128, 2), 256>>>(W_in, b_in);
    k_ctx<<<MCTX / 64, 256>>>(enc, W_ctx, b_ctx, Vv, mask);
    k_colred<<<Ll, 256>>>();
    k_final<<<(Bb + 255) / 256, 256>>>(mask, out);
}

// round 8
// speedup vs baseline: 1.1359x; 1.0643x over previous
#include <cuda_runtime.h>
#include <stdint.h>

// Problem constants
#define Bb    32768
#define Ll    7
#define Tt    6
#define Hh    256
#define TS    5                 // only edges t=0..4 are live
#define MROWS (Bb * TS)         // 163840
#define MCTX  (Bb * Ll)         // 229376

// ---------------- device scratch (static, allocation-free) ----------------
__device__ float g_Edge[(size_t)MROWS * Hh];
__device__ float g_qt  [Bb * Hh];
__device__ float g_inp [Bb * Hh];
__device__ float g_att2[MCTX];
__device__ float g_colmax[Ll];
__device__ float g_colsum[Ll];
__device__ float g_logZ[Ll];
__device__ int   g_rmap[MROWS];
__device__ int   g_hv  [MROWS];
__device__ int   g_cntA;
__device__ int   g_cntB;
__device__ int   g_is64;

// ---------------- small helpers ----------------
__device__ __forceinline__ unsigned long long pack2(float x, float y) {
    unsigned long long r;
    asm("mov.b64 %0, {%1, %2};" : "=l"(r) : "r"(__float_as_uint(x)), "r"(__float_as_uint(y)));
    return r;
}
__device__ __forceinline__ float2 unpack2(unsigned long long v) {
    unsigned int lo, hi;
    asm("mov.b64 {%0, %1}, %2;" : "=r"(lo), "=r"(hi) : "l"(v));
    float2 f; f.x = __uint_as_float(lo); f.y = __uint_as_float(hi); return f;
}
#define FMA2(acc, a, b) asm("fma.rn.f32x2 %0, %1, %2, %0;" : "+l"(acc) : "l"(a), "l"(b))

__device__ __forceinline__ uint32_t rotl32(uint32_t v, int r) { return (v << r) | (v >> (32 - r)); }

// JAX Threefry-2x32-20, key = (0, 42); partitionable stream, o0^o1 fold
__device__ __forceinline__ void tf2x32(uint32_t x0, uint32_t x1, uint32_t& o0, uint32_t& o1) {
    const uint32_t k0 = 0u, k1 = 42u, k2 = 0u ^ 42u ^ 0x1BD11BDAu;
    x0 += k0; x1 += k1;
#define TFR(r) { x0 += x1; x1 = rotl32(x1, (r)); x1 ^= x0; }
    TFR(13) TFR(15) TFR(26) TFR(6)   x0 += k1; x1 += k2 + 1u;
    TFR(17) TFR(29) TFR(16) TFR(24)  x0 += k2; x1 += k0 + 2u;
    TFR(13) TFR(15) TFR(26) TFR(6)   x0 += k0; x1 += k1 + 3u;
    TFR(17) TFR(29) TFR(16) TFR(24)  x0 += k1; x1 += k2 + 4u;
    TFR(13) TFR(15) TFR(26) TFR(6)   x0 += k2; x1 += k0 + 5u;
#undef TFR
    o0 = x0; o1 = x1;
}
__device__ __forceinline__ uint32_t jax_bits(uint32_t n) {
    uint32_t o0, o1; tf2x32(0u, n, o0, o1); return o0 ^ o1;
}

// ---------------- setup kernels ----------------
__global__ void k_init() { g_cntA = 0; g_cntB = 0; }

__global__ void k_detect(const int* __restrict__ xes) {
    __shared__ int any;
    if (threadIdx.x == 0) any = 0;
    __syncthreads();
    if (xes[2 * threadIdx.x + 1] != 0) any = 1;
    __syncthreads();
    if (threadIdx.x == 0) g_is64 = !any;
}

__global__ void k_map(const int* __restrict__ xes) {
    int bt = blockIdx.x * blockDim.x + threadIdx.x;
    if (bt >= MROWS) return;
    int b = bt / TS, t = bt - b * TS;
    int base = (b * Tt + t) * 3;
    int s = g_is64 ? 2 : 1;
    int h  = xes[(base + 0) * s];
    int v  = xes[(base + 1) * s];
    int tt = xes[(base + 2) * s];
    int g;
    if (tt == 0) g = atomicAdd(&g_cntA, 1);
    else         g = MROWS - 1 - atomicAdd(&g_cntB, 1);
    g_rmap[g] = bt;
    g_hv[g]   = h | (v << 8);
}

// ---------------- edge GEMM: fused gather, 16x8 microtile, pipelined ------
// 128 rows x 256 cols per block, 256 threads, K = 512 (h half then v half).
__global__ void __launch_bounds__(256, 1) k_edges(const float* __restrict__ enc,
                                                  const float* __restrict__ Wh,
                                                  const float* __restrict__ Wv,
                                                  const float* __restrict__ Wsh,
                                                  const float* __restrict__ Wsv) {
    const int row0 = blockIdx.x * 128;
    __shared__ __align__(16) float As[16][132];
    __shared__ __align__(16) float Bs[16][260];
    __shared__ const float* rpH[128];
    __shared__ const float* rpV[128];
    __shared__ int sbt[128];

    const int tid = threadIdx.x;
    if (tid < 128) {
        int g = row0 + tid;
        int bt = g_rmap[g];
        int hv = g_hv[g];
        int b = bt / TS;
        sbt[tid] = bt;
        rpH[tid] = enc + (size_t)(b * Ll + (hv & 255)) * 256;
        rpV[tid] = enc + (size_t)(b * Ll + (hv >> 8)) * 256;
    }
    __syncthreads();

    const int bound = g_cntA;
    const int tx = tid & 31, ty = tid >> 5;       // tx: 8 cols (256), ty: 16 rows (128)
    const int r0 = tid >> 2, ak = (tid & 3) * 4;  // loader mapping

    for (int pass = 0; pass < 2; pass++) {
        if (pass == 0 && row0 >= bound) continue;
        if (pass == 1 && row0 + 128 <= bound) continue;
        const float* WA = pass ? Wsh : Wh;
        const float* WB = pass ? Wsv : Wv;

        unsigned long long acc[16][4];
#pragma unroll
        for (int i = 0; i < 16; i++)
#pragma unroll
            for (int j = 0; j < 4; j++) acc[i][j] = 0ull;

        // preload kk = 0
        float4 a_st0 = *(const float4*)(rpH[r0] + ak);
        float4 a_st1 = *(const float4*)(rpH[r0 + 64] + ak);
        float4 b_st[4];
#pragma unroll
        for (int j = 0; j < 4; j++)
            b_st[j] = *(const float4*)(WA + (size_t)(r0 + j * 64) * 256 + ak);

        for (int kk = 0; kk < 512; kk += 16) {
            __syncthreads();
            As[ak + 0][r0] = a_st0.x; As[ak + 1][r0] = a_st0.y;
            As[ak + 2][r0] = a_st0.z; As[ak + 3][r0] = a_st0.w;
            As[ak + 0][r0 + 64] = a_st1.x; As[ak + 1][r0 + 64] = a_st1.y;
            As[ak + 2][r0 + 64] = a_st1.z; As[ak + 3][r0 + 64] = a_st1.w;
#pragma unroll
            for (int j = 0; j < 4; j++) {
                int n = r0 + j * 64;
                Bs[ak + 0][n] = b_st[j].x; Bs[ak + 1][n] = b_st[j].y;
                Bs[ak + 2][n] = b_st[j].z; Bs[ak + 3][n] = b_st[j].w;
            }
            __syncthreads();

            int kn = kk + 16;
            if (kn < 512) {
                int off = (kn & 255) + ak;
                const float* const* rp = (kn < 256) ? rpH : rpV;
                a_st0 = *(const float4*)(rp[r0] + off);
                a_st1 = *(const float4*)(rp[r0 + 64] + off);
                const float* Wp = (kn < 256) ? WA : WB;
#pragma unroll
                for (int j = 0; j < 4; j++)
                    b_st[j] = *(const float4*)(Wp + (size_t)(r0 + j * 64) * 256 + off);
            }

#pragma unroll
            for (int p = 0; p < 16; p++) {
                float4 b0 = *(const float4*)&Bs[p][tx * 8];
                float4 b1 = *(const float4*)&Bs[p][tx * 8 + 4];
                unsigned long long bb[4];
                bb[0] = pack2(b0.x, b0.y); bb[1] = pack2(b0.z, b0.w);
                bb[2] = pack2(b1.x, b1.y); bb[3] = pack2(b1.z, b1.w);
                float4 a0 = *(const float4*)&As[p][ty * 16];
                float4 a1 = *(const float4*)&As[p][ty * 16 + 4];
                float4 a2 = *(const float4*)&As[p][ty * 16 + 8];
                float4 a3 = *(const float4*)&As[p][ty * 16 + 12];
                float av[16] = {a0.x, a0.y, a0.z, a0.w, a1.x, a1.y, a1.z, a1.w,
                                a2.x, a2.y, a2.z, a2.w, a3.x, a3.y, a3.z, a3.w};
#pragma unroll
                for (int i = 0; i < 16; i++) {
                    unsigned long long aa = pack2(av[i], av[i]);
#pragma unroll
                    for (int j = 0; j < 4; j++) FMA2(acc[i][j], aa, bb[j]);
                }
            }
        }

#pragma unroll
        for (int i = 0; i < 16; i++) {
            int r = ty * 16 + i;
            int g = row0 + r;
            bool ok = (pass == 0) ? (g < bound) : (g >= bound);
            if (ok) {
                float c[8];
#pragma unroll
                for (int j = 0; j < 4; j++) {
                    float2 f = unpack2(acc[i][j]);
                    c[2 * j] = f.x; c[2 * j + 1] = f.y;
                }
                float* o = g_Edge + (size_t)sbt[r] * 256 + tx * 8;
                *(float4*)(o)     = make_float4(c[0], c[1], c[2], c[3]);
                *(float4*)(o + 4) = make_float4(c[4], c[5], c[6], c[7]);
            }
        }
    }
}

// ---------------- S GEMM fused with subtree-max + qt (unchanged R7) -------
__global__ void __launch_bounds__(256) k_subq(const float* __restrict__ We) {
    const int row0 = blockIdx.x * 160;
    const int col0 = blockIdx.y * 128;
    __shared__ __align__(16) float As[16][164];
    __shared__ __align__(16) float Bs[16][132];
    const int tid = threadIdx.x;
    const int tx = tid & 15, ty = tid >> 4;

    unsigned long long acc[10][4];
#pragma unroll
    for (int i = 0; i < 10; i++)
#pragma unroll
        for (int j = 0; j < 4; j++) acc[i][j] = 0ull;

    float4 a_st[3], b_st[2];
#pragma unroll
    for (int i = 0; i < 3; i++) {
        int idx = tid + i * 256;
        if (idx < 640) {
            int m = idx >> 2, kq = (idx & 3) * 4;
            a_st[i] = *(const float4*)(g_Edge + (size_t)(row0 + m) * 256 + kq);
        }
    }
#pragma unroll
    for (int i = 0; i < 2; i++) {
        int idx = tid + i * 256;
        int n = idx >> 2, kq = (idx & 3) * 4;
        b_st[i] = *(const float4*)(We + (size_t)(col0 + n) * 256 + kq);
    }

    for (int kk = 0; kk < 256; kk += 16) {
        __syncthreads();
#pragma unroll
        for (int i = 0; i < 3; i++) {
            int idx = tid + i * 256;
            if (idx < 640) {
                int m = idx >> 2, kq = (idx & 3) * 4;
                As[kq + 0][m] = a_st[i].x; As[kq + 1][m] = a_st[i].y;
                As[kq + 2][m] = a_st[i].z; As[kq + 3][m] = a_st[i].w;
            }
        }
#pragma unroll
        for (int i = 0; i < 2; i++) {
            int idx = tid + i * 256;
            int n = idx >> 2, kq = (idx & 3) * 4;
            Bs[kq + 0][n] = b_st[i].x; Bs[kq + 1][n] = b_st[i].y;
            Bs[kq + 2][n] = b_st[i].z; Bs[kq + 3][n] = b_st[i].w;
        }
        __syncthreads();

        int kn = kk + 16;
        if (kn < 256) {
#pragma unroll
            for (int i = 0; i < 3; i++) {
                int idx = tid + i * 256;
                if (idx < 640) {
                    int m = idx >> 2, kq = (idx & 3) * 4;
                    a_st[i] = *(const float4*)(g_Edge + (size_t)(row0 + m) * 256 + kn + kq);
                }
            }
#pragma unroll
            for (int i = 0; i < 2; i++) {
                int idx = tid + i * 256;
                int n = idx >> 2, kq = (idx & 3) * 4;
                b_st[i] = *(const float4*)(We + (size_t)(col0 + n) * 256 + kn + kq);
            }
        }

#pragma unroll
        for (int p = 0; p < 16; p++) {
            float av[10];
#pragma unroll
            for (int i = 0; i < 10; i += 2) {
                float2 t2 = *(const float2*)&As[p][ty * 10 + i];
                av[i] = t2.x; av[i + 1] = t2.y;
            }
            float4 b0 = *(const float4*)&Bs[p][tx * 8];
            float4 b1 = *(const float4*)&Bs[p][tx * 8 + 4];
            unsigned long long bb[4];
            bb[0] = pack2(b0.x, b0.y); bb[1] = pack2(b0.z, b0.w);
            bb[2] = pack2(b1.x, b1.y); bb[3] = pack2(b1.z, b1.w);
#pragma unroll
            for (int i = 0; i < 10; i++) {
                unsigned long long aa = pack2(av[i], av[i]);
#pragma unroll
                for (int j = 0; j < 4; j++) FMA2(acc[i][j], aa, bb[j]);
            }
        }
    }

#pragma unroll
    for (int grp = 0; grp < 2; grp++) {
        int gr = row0 + ty * 10 + grp * 5;
        int b = gr / 5;
        float mx[8];
#pragma unroll
        for (int c = 0; c < 8; c++) mx[c] = 0.f;
#pragma unroll
        for (int i = 0; i < 5; i++) {
#pragma unroll
            for (int j = 0; j < 4; j++) {
                float2 f = unpack2(acc[grp * 5 + i][j]);
                mx[2 * j]     = fmaxf(mx[2 * j],     f.x);
                mx[2 * j + 1] = fmaxf(mx[2 * j + 1], f.y);
            }
        }
        const float* e4 = g_Edge + (size_t)(gr + 4) * 256 + col0 + tx * 8;
        float4 e0 = *(const float4*)(e4);
        float4 e1 = *(const float4*)(e4 + 4);
        float q[8];
        q[0] = fmaxf(e0.x + mx[0], 0.f); q[1] = fmaxf(e0.y + mx[1], 0.f);
        q[2] = fmaxf(e0.z + mx[2], 0.f); q[3] = fmaxf(e0.w + mx[3], 0.f);
        q[4] = fmaxf(e1.x + mx[4], 0.f); q[5] = fmaxf(e1.y + mx[5], 0.f);
        q[6] = fmaxf(e1.z + mx[6], 0.f); q[7] = fmaxf(e1.w + mx[7], 0.f);
        float* o = g_qt + (size_t)b * 256 + col0 + tx * 8;
        *(float4*)(o)     = make_float4(q[0], q[1], q[2], q[3]);
        *(float4*)(o + 4) = make_float4(q[4], q[5], q[6], q[7]);
    }
}

// ---------------- inp = qt @ W_in^T + b_in (unchanged R7) -----------------
__global__ void __launch_bounds__(256) k_inp(const float* __restrict__ Wi,
                                             const float* __restrict__ bi) {
    const int row0 = blockIdx.x * 128;
    const int col0 = blockIdx.y * 128;
    __shared__ __align__(16) float As[16][132];
    __shared__ __align__(16) float Bs[16][132];
    const int tid = threadIdx.x;
    const int tx = tid & 15, ty = tid >> 4;

    unsigned long long acc[8][4];
#pragma unroll
    for (int i = 0; i < 8; i++)
#pragma unroll
        for (int j = 0; j < 4; j++) acc[i][j] = 0ull;

    float4 a_st[2], b_st[2];
#pragma unroll
    for (int i = 0; i < 2; i++) {
        int idx = tid + i * 256;
        int m = idx >> 2, kq = (idx & 3) * 4;
        a_st[i] = *(const float4*)(g_qt + (size_t)(row0 + m) * 256 + kq);
        b_st[i] = *(const float4*)(Wi + (size_t)(col0 + m) * 256 + kq);
    }

    for (int kk = 0; kk < 256; kk += 16) {
        __syncthreads();
#pragma unroll
        for (int i = 0; i < 2; i++) {
            int idx = tid + i * 256;
            int m = idx >> 2, kq = (idx & 3) * 4;
            As[kq + 0][m] = a_st[i].x; As[kq + 1][m] = a_st[i].y;
            As[kq + 2][m] = a_st[i].z; As[kq + 3][m] = a_st[i].w;
            Bs[kq + 0][m] = b_st[i].x; Bs[kq + 1][m] = b_st[i].y;
            Bs[kq + 2][m] = b_st[i].z; Bs[kq + 3][m] = b_st[i].w;
        }
        __syncthreads();

        int kn = kk + 16;
        if (kn < 256) {
#pragma unroll
            for (int i = 0; i < 2; i++) {
                int idx = tid + i * 256;
                int m = idx >> 2, kq = (idx & 3) * 4;
                a_st[i] = *(const float4*)(g_qt + (size_t)(row0 + m) * 256 + kn + kq);
                b_st[i] = *(const float4*)(Wi + (size_t)(col0 + m) * 256 + kn + kq);
            }
        }

#pragma unroll
        for (int p = 0; p < 16; p++) {
            float4 a0 = *(const float4*)&As[p][ty * 8];
            float4 a1 = *(const float4*)&As[p][ty * 8 + 4];
            float4 b0 = *(const float4*)&Bs[p][tx * 8];
            float4 b1 = *(const float4*)&Bs[p][tx * 8 + 4];
            unsigned long long bb[4];
            bb[0] = pack2(b0.x, b0.y); bb[1] = pack2(b0.z, b0.w);
            bb[2] = pack2(b1.x, b1.y); bb[3] = pack2(b1.z, b1.w);
            float av[8] = {a0.x, a0.y, a0.z, a0.w, a1.x, a1.y, a1.z, a1.w};
#pragma unroll
            for (int i = 0; i < 8; i++) {
                unsigned long long aa = pack2(av[i], av[i]);
#pragma unroll
                for (int j = 0; j < 4; j++) FMA2(acc[i][j], aa, bb[j]);
            }
        }
    }

#pragma unroll
    for (int i = 0; i < 8; i++) {
        int r = row0 + ty * 8 + i;
        float c[8];
#pragma unroll
        for (int j = 0; j < 4; j++) {
            float2 f = unpack2(acc[i][j]);
            c[2 * j] = f.x; c[2 * j + 1] = f.y;
        }
        const float* bp = bi + col0 + tx * 8;
#pragma unroll
        for (int j = 0; j < 8; j++) c[j] += bp[j];
        float* o = g_inp + (size_t)r * 256 + col0 + tx * 8;
        *(float4*)(o)     = make_float4(c[0], c[1], c[2], c[3]);
        *(float4*)(o + 4) = make_float4(c[4], c[5], c[6], c[7]);
    }
}

// ---------------- ctx GEMM fused with att2: 16x8 microtile, 128x256 tile --
__global__ void __launch_bounds__(256, 1) k_ctx(const float* __restrict__ A,
                                                const float* __restrict__ W,
                                                const float* __restrict__ bias,
                                                const float* __restrict__ Vv,
                                                const int* __restrict__ mask) {
    const int row0 = blockIdx.x * 128;
    __shared__ __align__(16) float As[16][132];
    __shared__ __align__(16) float Bs[16][260];
    const int tid = threadIdx.x;
    const int tx = tid & 31, ty = tid >> 5;       // tx: 8 cols (256), ty: 16 rows (128)
    const int r0 = tid >> 2, ak = (tid & 3) * 4;

    unsigned long long acc[16][4];
#pragma unroll
    for (int i = 0; i < 16; i++)
#pragma unroll
        for (int j = 0; j < 4; j++) acc[i][j] = 0ull;

    float4 a_st0 = *(const float4*)(A + (size_t)(row0 + r0) * 256 + ak);
    float4 a_st1 = *(const float4*)(A + (size_t)(row0 + r0 + 64) * 256 + ak);
    float4 b_st[4];
#pragma unroll
    for (int j = 0; j < 4; j++)
        b_st[j] = *(const float4*)(W + (size_t)(r0 + j * 64) * 256 + ak);

    for (int kk = 0; kk < 256; kk += 16) {
        __syncthreads();
        As[ak + 0][r0] = a_st0.x; As[ak + 1][r0] = a_st0.y;
        As[ak + 2][r0] = a_st0.z; As[ak + 3][r0] = a_st0.w;
        As[ak + 0][r0 + 64] = a_st1.x; As[ak + 1][r0 + 64] = a_st1.y;
        As[ak + 2][r0 + 64] = a_st1.z; As[ak + 3][r0 + 64] = a_st1.w;
#pragma unroll
        for (int j = 0; j < 4; j++) {
            int n = r0 + j * 64;
            Bs[ak + 0][n] = b_st[j].x; Bs[ak + 1][n] = b_st[j].y;
            Bs[ak + 2][n] = b_st[j].z; Bs[ak + 3][n] = b_st[j].w;
        }
        __syncthreads();

        int kn = kk + 16;
        if (kn < 256) {
            a_st0 = *(const float4*)(A + (size_t)(row0 + r0) * 256 + kn + ak);
            a_st1 = *(const float4*)(A + (size_t)(row0 + r0 + 64) * 256 + kn + ak);
#pragma unroll
            for (int j = 0; j < 4; j++)
                b_st[j] = *(const float4*)(W + (size_t)(r0 + j * 64) * 256 + kn + ak);
        }

#pragma unroll
        for (int p = 0; p < 16; p++) {
            float4 b0 = *(const float4*)&Bs[p][tx * 8];
            float4 b1 = *(const float4*)&Bs[p][tx * 8 + 4];
            unsigned long long bb[4];
            bb[0] = pack2(b0.x, b0.y); bb[1] = pack2(b0.z, b0.w);
            bb[2] = pack2(b1.x, b1.y); bb[3] = pack2(b1.z, b1.w);
            float4 a0 = *(const float4*)&As[p][ty * 16];
            float4 a1 = *(const float4*)&As[p][ty * 16 + 4];
            float4 a2 = *(const float4*)&As[p][ty * 16 + 8];
            float4 a3 = *(const float4*)&As[p][ty * 16 + 12];
            float av[16] = {a0.x, a0.y, a0.z, a0.w, a1.x, a1.y, a1.z, a1.w,
                            a2.x, a2.y, a2.z, a2.w, a3.x, a3.y, a3.z, a3.w};
#pragma unroll
            for (int i = 0; i < 16; i++) {
                unsigned long long aa = pack2(av[i], av[i]);
#pragma unroll
                for (int j = 0; j < 4; j++) FMA2(acc[i][j], aa, bb[j]);
            }
        }
    }

    float bc[8], vv[8];
#pragma unroll
    for (int j = 0; j < 8; j++) { bc[j] = bias[tx * 8 + j]; vv[j] = Vv[tx * 8 + j]; }

#pragma unroll
    for (int i = 0; i < 16; i++) {
        int m = row0 + ty * 16 + i;
        int b = m / Ll;
        const float* ip = g_inp + (size_t)b * 256 + tx * 8;
        float s = 0.f;
#pragma unroll
        for (int j = 0; j < 4; j++) {
            float2 cf = unpack2(acc[i][j]);
            int jj = 2 * j;
            s += vv[jj]     * tanhf(ip[jj]     + (cf.x + bc[jj]));
            s += vv[jj + 1] * tanhf(ip[jj + 1] + (cf.y + bc[jj + 1]));
        }
#pragma unroll
        for (int o = 16; o > 0; o >>= 1) s += __shfl_xor_sync(0xffffffffu, s, o);
        if (tx == 0) {
            if (mask[m] == 0) s = -1000000000.0f;
            g_att2[m] = 10.0f * tanhf(s);
        }
    }
}

// ---------------- per-column softmax stats over batch axis ----------------
__global__ void k_colred() {
    const int l = blockIdx.x;
    __shared__ float red[256];
    float mx = __int_as_float(0xff800000);
    for (int b = threadIdx.x; b < Bb; b += 256) mx = fmaxf(mx, g_att2[b * Ll + l]);
    red[threadIdx.x] = mx; __syncthreads();
    for (int o = 128; o > 0; o >>= 1) {
        if (threadIdx.x < o) red[threadIdx.x] = fmaxf(red[threadIdx.x], red[threadIdx.x + o]);
        __syncthreads();
    }
    mx = red[0]; __syncthreads();
    float sum = 0.f;
    for (int b = threadIdx.x; b < Bb; b += 256) sum += expf(g_att2[b * Ll + l] - mx);
    red[threadIdx.x] = sum; __syncthreads();
    for (int o = 128; o > 0; o >>= 1) {
        if (threadIdx.x < o) red[threadIdx.x] += red[threadIdx.x + o];
        __syncthreads();
    }
    if (threadIdx.x == 0) {
        g_colmax[l] = mx;
        g_colsum[l] = red[0];
        g_logZ[l]   = mx + logf(red[0]);
    }
}

// ---------------- Gumbel-argmax + p + new_mask ----------------------------
__global__ void k_final(const int* __restrict__ mask, float* __restrict__ out) {
    int b = blockIdx.x * blockDim.x + threadIdx.x;
    if (b >= Bb) return;
    const float TINY = 1.17549435e-38f;
    float best = __int_as_float(0xff800000);
    int idx = 0;
    float a2[Ll];
#pragma unroll
    for (int l = 0; l < Ll; l++) {
        float a = g_att2[b * Ll + l];
        a2[l] = a;
        float la = a - g_logZ[l];
        uint32_t bits = jax_bits((uint32_t)(b * Ll + l));
        float fl = __uint_as_float((bits >> 9) | 0x3F800000u) - 1.0f;
        float u  = fmaxf(TINY, fl + TINY);
        float g  = -logf(-logf(u));
        float s  = la + g;
        if (s > best) { best = s; idx = l; }
    }
    float p = expf(a2[idx] - g_colmax[idx]) / g_colsum[idx];
    out[b]      = (float)idx;
    out[Bb + b] = p;
#pragma unroll
    for (int l = 0; l < Ll; l++)
        out[2 * Bb + b * Ll + l] = (float)(mask[b * Ll + l] - (l == idx ? 1 : 0));
}

// ---------------- launcher ----------------
extern "C" void kernel_launch(void* const* d_in, const int* in_sizes, int n_in,
                              void* d_out, int out_size) {
    const float* enc    = (const float*)d_in[0];
    const int*   xes    = (const int*)  d_in[1];
    const int*   mask   = (const int*)  d_in[2];
    const float* W_h    = (const float*)d_in[3];
    const float* W_v    = (const float*)d_in[4];
    const float* Ws_h   = (const float*)d_in[5];
    const float* Ws_v   = (const float*)d_in[6];
    const float* W_edge = (const float*)d_in[7];
    const float* W_in   = (const float*)d_in[8];
    const float* b_in   = (const float*)d_in[9];
    const float* W_ctx  = (const float*)d_in[10];
    const float* b_ctx  = (const float*)d_in[11];
    const float* Vv     = (const float*)d_in[12];
    float* out = (float*)d_out;

    k_init<<<1, 1>>>();
    k_detect<<<1, 128>>>(xes);
    k_map<<<(MROWS + 255) / 256, 256>>>(xes);

    k_edges<<<MROWS / 128, 256>>>(enc, W_h, W_v, Ws_h, Ws_v);
    k_subq<<<dim3(MROWS / 160, 2), 256>>>(W_edge);
    k_inp<<<dim3(Bb / 128, 2), 256>>>(W_in, b_in);
    k_ctx<<<MCTX / 128, 256>>>(enc, W_ctx, b_ctx, Vv, mask);
    k_colred<<<Ll, 256>>>();
    k_final<<<(Bb + 255) / 256, 256>>>(mask, out);
}